// round 8
// baseline (speedup 1.0000x reference)
#include <cuda_runtime.h>
#include <cuda_fp16.h>
#include <cstdint>

// Problem constants
#define NNODES 20000
#define NEDGES 200000
#define D_IN   1433
#define D_H1   1000
#define D_H2   500
#define D_OUT  7

// Padded GEMM dims
#define K1PAD  1472   // >= 1433, mult of 64
#define K2PAD  1024   // >= 1000, mult of 64
#define N1PAD  1024   // >= 1000, mult of 128
#define N2PAD  512    // >= 500,  mult of 128

// ---------------------------------------------------------------------------
// Device scratch
// ---------------------------------------------------------------------------
__device__ __align__(256) __half g_fa[(size_t)NNODES * K1PAD];
__device__ __align__(256) __half g_w1t[(size_t)N1PAD * K1PAD];
__device__ __align__(256) __half g_x1[(size_t)NNODES * K2PAD];
__device__ __align__(256) __half g_w2t[(size_t)N2PAD * K2PAD];
__device__ __align__(256) __half g_t1[(size_t)NNODES * D_H1];
__device__ __align__(256) __half g_t2[(size_t)NNODES * D_H2];
__device__ __align__(256) float  g_x2[(size_t)NNODES * D_H2];
__device__ int g_count[NNODES];
__device__ int g_pos[NNODES];
__device__ int g_offs[NNODES + 1];
__device__ int g_eidx[NEDGES];

// ---------------------------------------------------------------------------
// PTX helpers
// ---------------------------------------------------------------------------
__device__ __forceinline__ uint32_t smem_to_u32(const void* p) {
    uint32_t a;
    asm("{ .reg .u64 t; cvta.to.shared.u64 t, %1; cvt.u32.u64 %0, t; }"
        : "=r"(a) : "l"(p));
    return a;
}

__device__ __forceinline__ void cp_async16(uint32_t sdst, const void* gsrc, bool ok) {
    int sz = ok ? 16 : 0;
    asm volatile("cp.async.cg.shared.global [%0], [%1], 16, %2;\n"
                 :: "r"(sdst), "l"(gsrc), "r"(sz));
}
#define CP_COMMIT() asm volatile("cp.async.commit_group;\n" ::: "memory")
#define CP_WAIT(n)  asm volatile("cp.async.wait_group %0;\n" :: "n"(n) : "memory")

__device__ __forceinline__ void ldm_x4(uint32_t& r0, uint32_t& r1, uint32_t& r2,
                                       uint32_t& r3, uint32_t addr) {
    asm volatile("ldmatrix.sync.aligned.m8n8.x4.shared.b16 {%0,%1,%2,%3}, [%4];"
                 : "=r"(r0), "=r"(r1), "=r"(r2), "=r"(r3) : "r"(addr));
}

__device__ __forceinline__ void mma_f16(float* c, const uint32_t* a, const uint32_t* b) {
    asm volatile(
        "mma.sync.aligned.m16n8k16.row.col.f32.f16.f16.f32 "
        "{%0,%1,%2,%3}, {%4,%5,%6,%7}, {%8,%9}, {%0,%1,%2,%3};"
        : "+f"(c[0]), "+f"(c[1]), "+f"(c[2]), "+f"(c[3])
        : "r"(a[0]), "r"(a[1]), "r"(a[2]), "r"(a[3]), "r"(b[0]), "r"(b[1]));
}

__device__ __forceinline__ uint32_t pack_f16x2(float a, float b) {
    __half2 h = __floats2half2_rn(a, b);
    return *reinterpret_cast<uint32_t*>(&h);
}

struct __align__(8) half4 { __half2 a, b; };

// ---------------------------------------------------------------------------
// CSR build
// ---------------------------------------------------------------------------
__global__ void zero_counts_kernel() {
    int i = blockIdx.x * blockDim.x + threadIdx.x;
    if (i < NNODES) { g_count[i] = 0; g_pos[i] = 0; }
}
__global__ void count_kernel(const int* __restrict__ dst) {
    int e = blockIdx.x * blockDim.x + threadIdx.x;
    if (e < NEDGES) atomicAdd(&g_count[dst[e]], 1);
}
__global__ void scan_kernel() {
    __shared__ int part[1024];
    const int tid = threadIdx.x;
    const int CH = (NNODES + 1023) / 1024;
    const int base = tid * CH;
    int s = 0;
    for (int i = 0; i < CH; ++i) {
        int idx = base + i;
        if (idx < NNODES) s += g_count[idx];
    }
    part[tid] = s;
    __syncthreads();
    for (int off = 1; off < 1024; off <<= 1) {
        int v = (tid >= off) ? part[tid - off] : 0;
        __syncthreads();
        part[tid] += v;
        __syncthreads();
    }
    int run = part[tid] - s;
    for (int i = 0; i < CH; ++i) {
        int idx = base + i;
        if (idx < NNODES) { g_offs[idx] = run; run += g_count[idx]; }
    }
    if (tid == 1023) g_offs[NNODES] = part[1023];
}
__global__ void fill_kernel(const int* __restrict__ src, const int* __restrict__ dst) {
    int e = blockIdx.x * blockDim.x + threadIdx.x;
    if (e < NEDGES) {
        int d = dst[e];
        int p = atomicAdd(&g_pos[d], 1);
        g_eidx[g_offs[d] + p] = src[e];
    }
}

// ---------------------------------------------------------------------------
// Conversion: fp32 -> fp16, zero-padded; 4 elems/thread
// ---------------------------------------------------------------------------
__global__ void quantize_pad_kernel(const float* __restrict__ src,
                                    __half* __restrict__ dstq,
                                    int M, int K, int Kpad) {
    size_t idx4 = (size_t)blockIdx.x * blockDim.x + threadIdx.x;
    size_t total4 = (size_t)M * (Kpad >> 2);
    if (idx4 >= total4) return;
    int gpr = Kpad >> 2;
    int r = (int)(idx4 / gpr);
    int c = (int)(idx4 % gpr) << 2;
    float v[4];
#pragma unroll
    for (int j = 0; j < 4; ++j) {
        int cj = c + j;
        v[j] = (cj < K) ? src[(size_t)r * K + cj] : 0.f;
    }
    size_t o = (size_t)r * Kpad + c;
    *reinterpret_cast<uint2*>(dstq + o) =
        make_uint2(pack_f16x2(v[0], v[1]), pack_f16x2(v[2], v[3]));
}

// Tiled transpose: W [K,N] fp32 row-major -> Wt fp16 [Npad][Kpad], zero-padded
__global__ void transpose_f16_tiled_kernel(const float* __restrict__ W,
                                           __half* __restrict__ t,
                                           int K, int N, int Kpad, int Npad) {
    __shared__ float tile[32][33];
    const int k0 = blockIdx.x * 32;
    const int n0 = blockIdx.y * 32;
    const int tx = threadIdx.x;        // 0..31
    const int ty = threadIdx.y;        // 0..7
#pragma unroll
    for (int j = 0; j < 32; j += 8) {
        int k = k0 + ty + j, n = n0 + tx;
        tile[ty + j][tx] = (k < K && n < N) ? W[(size_t)k * N + n] : 0.f;
    }
    __syncthreads();
#pragma unroll
    for (int j = 0; j < 32; j += 8) {
        int n = n0 + ty + j, k = k0 + tx;
        if (n < Npad && k < Kpad)
            t[(size_t)n * Kpad + k] = __float2half(tile[tx][ty + j]);
    }
}

// ---------------------------------------------------------------------------
// HMMA GEMM: CTA tile 256x128, 8 warps (4m x 2n), warp tile 64x64.
// 3-stage cp.async pipeline, BK=64, single-pass fp16, fp32 accum, fp16 out.
// SMEM rows padded to 72 halves (conflict-free ldmatrix).
// Design point: MMA:LDSM = 4.0 (vs 2.67 for 32x64) -> LDSM floor no longer binds.
// ---------------------------------------------------------------------------
#define BK 64
#define ROW_H 72                                 // halves per smem row (64 + 8)
#define A_ROWS 256
#define B_ROWS 128
#define A_MAT ((uint32_t)(A_ROWS * ROW_H * 2))   // 36864
#define B_MAT ((uint32_t)(B_ROWS * ROW_H * 2))   // 18432
#define B_OFF A_MAT
#define STAGE_BYTES (A_MAT + B_MAT)              // 55296
#define NSTAGE 3
#define GEMM_SMEM (NSTAGE * STAGE_BYTES)         // 165888

__global__ __launch_bounds__(256, 1)
void hmma_gemm_f16_kernel(const __half* __restrict__ a,
                          const __half* __restrict__ b,
                          __half* __restrict__ C,
                          int M, int Nreal, int Kpad) {
    extern __shared__ __half smem[];
    const uint32_t smem_u32 = smem_to_u32(smem);
    const int t = threadIdx.x;
    const int lane = t & 31;
    const int wid = t >> 5;
    const int wm = wid & 3;          // 4 warps in m -> rows wm*64
    const int wn = wid >> 2;         // 2 warps in n -> cols wn*64
    const int m0 = blockIdx.y * A_ROWS;
    const int n0 = blockIdx.x * B_ROWS;
    const int nchunk = Kpad / BK;

    float acc[4][8][4];
#pragma unroll
    for (int i = 0; i < 4; ++i)
#pragma unroll
        for (int j = 0; j < 8; ++j)
#pragma unroll
            for (int k = 0; k < 4; ++k) acc[i][j][k] = 0.f;

    auto load_stage = [&](int c) {
        const int slot = c % NSTAGE;
        const int k0 = c * BK;
        const uint32_t sbase = smem_u32 + slot * STAGE_BYTES;
        // A: 256 rows x 8 chunks = 2048 16B-chunks, 8 iters of 256 threads
#pragma unroll
        for (int i = 0; i < 8; ++i) {
            int idx = t + i * 256;
            int row = idx >> 3;
            int ch = idx & 7;
            uint32_t off = (uint32_t)(row * ROW_H + ch * 8) * 2;
            int gm = m0 + row;
            bool ok = gm < M;
            int gmc = ok ? gm : 0;
            size_t goa = (size_t)gmc * Kpad + k0 + ch * 8;
            cp_async16(sbase + off, a + goa, ok);
        }
        // B: 128 rows x 8 chunks = 1024 chunks, 4 iters
#pragma unroll
        for (int i = 0; i < 4; ++i) {
            int idx = t + i * 256;
            int row = idx >> 3;
            int ch = idx & 7;
            uint32_t off = (uint32_t)(row * ROW_H + ch * 8) * 2;
            size_t gob = (size_t)(n0 + row) * Kpad + k0 + ch * 8;
            cp_async16(sbase + B_OFF + off, b + gob, true);
        }
        CP_COMMIT();
    };

    // prologue: two stages in flight
    load_stage(0);
    if (nchunk > 1) load_stage(1);

    for (int c = 0; c < nchunk; ++c) {
        if (c + 1 < nchunk) { CP_WAIT(1); } else { CP_WAIT(0); }
        __syncthreads();   // stage c ready; all warps done with compute(c-1)
        if (c + 2 < nchunk) load_stage(c + 2);   // slot (c-1)%3, now free

        const uint32_t sb = smem_u32 + (uint32_t)(c % NSTAGE) * STAGE_BYTES;
#pragma unroll
        for (int ks = 0; ks < 4; ++ks) {
            const int k0s = ks * 16;
            // A fragments: 4 m16 tiles
            uint32_t af[4][4];
            {
                int ar = lane & 15;
                int ak = k0s + (lane >> 4) * 8;
#pragma unroll
                for (int mt = 0; mt < 4; ++mt) {
                    uint32_t addr = sb +
                        (uint32_t)((wm * 64 + mt * 16 + ar) * ROW_H + ak) * 2;
                    ldm_x4(af[mt][0], af[mt][1], af[mt][2], af[mt][3], addr);
                }
            }
            // B fragments: 8 n8 tiles (4 ldmatrix.x4)
            uint32_t bf[8][2];
            {
                int brr = (lane & 7) + (lane >> 4) * 8;
                int bk = k0s + ((lane >> 3) & 1) * 8;
#pragma unroll
                for (int ng = 0; ng < 4; ++ng) {
                    uint32_t addr = sb + B_OFF +
                        (uint32_t)((wn * 64 + ng * 16 + brr) * ROW_H + bk) * 2;
                    uint32_t r0, r1, r2, r3;
                    ldm_x4(r0, r1, r2, r3, addr);
                    bf[2 * ng][0] = r0; bf[2 * ng][1] = r1;
                    bf[2 * ng + 1][0] = r2; bf[2 * ng + 1][1] = r3;
                }
            }
#pragma unroll
            for (int mt = 0; mt < 4; ++mt) {
#pragma unroll
                for (int nt = 0; nt < 8; ++nt) {
                    mma_f16(acc[mt][nt], af[mt], bf[nt]);
                }
            }
        }
    }

    // epilogue: fp16 packed stores
#pragma unroll
    for (int mt = 0; mt < 4; ++mt) {
        int gr0 = m0 + wm * 64 + mt * 16 + (lane >> 2);
#pragma unroll
        for (int nt = 0; nt < 8; ++nt) {
            int gc = n0 + wn * 64 + nt * 8 + (lane & 3) * 2;
            if (gc >= Nreal) continue;   // Nreal even -> pair never straddles
            if (gr0 < M) {
                *reinterpret_cast<uint32_t*>(&C[(size_t)gr0 * Nreal + gc]) =
                    pack_f16x2(acc[mt][nt][0], acc[mt][nt][1]);
            }
            if (gr0 + 8 < M) {
                *reinterpret_cast<uint32_t*>(&C[(size_t)(gr0 + 8) * Nreal + gc]) =
                    pack_f16x2(acc[mt][nt][2], acc[mt][nt][3]);
            }
        }
    }
}

// ---------------------------------------------------------------------------
// Aggregation 1: x1[i,:] = relu(b1 + sum_j t1[j,:]) -> fp16, padded to K2PAD
// 128 threads/node, 8 halves (16B) per thread; fp32 accumulation.
// ---------------------------------------------------------------------------
__global__ __launch_bounds__(128)
void agg1_kernel(const __half* __restrict__ t,
                 const float* __restrict__ bias,
                 __half* __restrict__ x1) {
    __shared__ int nbr[512];
    const int node = blockIdx.x;
    const int beg = g_offs[node], end = g_offs[node + 1];
    const int deg = end - beg;
    const int* elist;
    if (deg <= 512) {
        for (int i = threadIdx.x; i < deg; i += blockDim.x) nbr[i] = g_eidx[beg + i];
        __syncthreads();
        elist = nbr;
    } else {
        elist = g_eidx + beg;
    }
    const int c = threadIdx.x << 3;       // 0..1016
    if (c < D_H1) {                       // threads 0..124 (1000 = 125*8)
        float a[8];
#pragma unroll
        for (int j = 0; j < 8; ++j) a[j] = bias[c + j];
        for (int e = 0; e < deg; ++e) {
            const uint4 v = *reinterpret_cast<const uint4*>(
                t + (size_t)elist[e] * D_H1 + c);
            const __half2* h = reinterpret_cast<const __half2*>(&v);
#pragma unroll
            for (int j = 0; j < 4; ++j) {
                float2 p = __half22float2(h[j]);
                a[2 * j] += p.x;
                a[2 * j + 1] += p.y;
            }
        }
        uint4 o;
        uint32_t* ow = reinterpret_cast<uint32_t*>(&o);
#pragma unroll
        for (int j = 0; j < 4; ++j)
            ow[j] = pack_f16x2(fmaxf(a[2 * j], 0.f), fmaxf(a[2 * j + 1], 0.f));
        *reinterpret_cast<uint4*>(x1 + (size_t)node * K2PAD + c) = o;
    } else {
        *reinterpret_cast<uint4*>(x1 + (size_t)node * K2PAD + c) =
            make_uint4(0u, 0u, 0u, 0u);
    }
}

// Aggregation 2: x2[i,:] = relu(b2 + sum_j t2[j,:]) -> fp32. 128 thr/node.
__global__ __launch_bounds__(128)
void agg2_kernel(const __half* __restrict__ t,
                 const float* __restrict__ bias,
                 float* __restrict__ out) {
    __shared__ int nbr[512];
    const int node = blockIdx.x;
    const int beg = g_offs[node], end = g_offs[node + 1];
    const int deg = end - beg;
    const int* elist;
    if (deg <= 512) {
        for (int i = threadIdx.x; i < deg; i += blockDim.x) nbr[i] = g_eidx[beg + i];
        __syncthreads();
        elist = nbr;
    } else {
        elist = g_eidx + beg;
    }
    const int c = threadIdx.x << 2;
    if (c >= D_H2) return;     // D_H2 = 500 -> 125 groups
    float a0 = bias[c], a1 = bias[c + 1], a2 = bias[c + 2], a3 = bias[c + 3];
    for (int e = 0; e < deg; ++e) {
        const half4 v = *reinterpret_cast<const half4*>(
            t + (size_t)elist[e] * D_H2 + c);
        float2 p = __half22float2(v.a);
        float2 q = __half22float2(v.b);
        a0 += p.x; a1 += p.y; a2 += q.x; a3 += q.y;
    }
    float4 r = make_float4(fmaxf(a0, 0.f), fmaxf(a1, 0.f),
                           fmaxf(a2, 0.f), fmaxf(a3, 0.f));
    *reinterpret_cast<float4*>(out + (size_t)node * D_H2 + c) = r;
}

// ---------------------------------------------------------------------------
// Output layer: out[i,:7] = relu(x2[i,:] @ W3 + b3), one warp per row
// ---------------------------------------------------------------------------
__global__ void out_layer_kernel(const float* __restrict__ x2,
                                 const float* __restrict__ W3,
                                 const float* __restrict__ b3,
                                 float* __restrict__ out) {
    __shared__ float Ws[D_H2 * D_OUT];
    for (int i = threadIdx.x; i < D_H2 * D_OUT; i += blockDim.x) Ws[i] = W3[i];
    __syncthreads();
    const int warp = (blockIdx.x * blockDim.x + threadIdx.x) >> 5;
    const int lane = threadIdx.x & 31;
    if (warp >= NNODES) return;
    float acc[D_OUT] = {0.f, 0.f, 0.f, 0.f, 0.f, 0.f, 0.f};
    const float* row = x2 + (size_t)warp * D_H2;
    for (int k = lane; k < D_H2; k += 32) {
        float v = row[k];
#pragma unroll
        for (int j = 0; j < D_OUT; ++j) acc[j] += v * Ws[k * D_OUT + j];
    }
#pragma unroll
    for (int j = 0; j < D_OUT; ++j) {
#pragma unroll
        for (int off = 16; off > 0; off >>= 1)
            acc[j] += __shfl_xor_sync(0xFFFFFFFFu, acc[j], off);
    }
    if (lane == 0) {
#pragma unroll
        for (int j = 0; j < D_OUT; ++j)
            out[(size_t)warp * D_OUT + j] = fmaxf(acc[j] + b3[j], 0.f);
    }
}

// ---------------------------------------------------------------------------
// Launch — conversions + gemm1 first (gemm1 stays on the ncu capture slot).
// ---------------------------------------------------------------------------
extern "C" void kernel_launch(void* const* d_in, const int* in_sizes, int n_in,
                              void* d_out, int out_size) {
    const float* features = (const float*)d_in[0];
    const int*   src      = (const int*)  d_in[1];
    const int*   dst      = (const int*)  d_in[2];
    const float* W1       = (const float*)d_in[3];
    const float* b1       = (const float*)d_in[4];
    const float* W2       = (const float*)d_in[5];
    const float* b2       = (const float*)d_in[6];
    const float* W3       = (const float*)d_in[7];
    const float* b3       = (const float*)d_in[8];
    float* out = (float*)d_out;

    __half *fa, *w1t, *x1, *w2t, *t1, *t2;
    float *x2;
    cudaGetSymbolAddress((void**)&fa, g_fa);
    cudaGetSymbolAddress((void**)&w1t, g_w1t);
    cudaGetSymbolAddress((void**)&x1, g_x1);
    cudaGetSymbolAddress((void**)&w2t, g_w2t);
    cudaGetSymbolAddress((void**)&t1, g_t1);
    cudaGetSymbolAddress((void**)&t2, g_t2);
    cudaGetSymbolAddress((void**)&x2, g_x2);

    cudaFuncSetAttribute(hmma_gemm_f16_kernel,
                         cudaFuncAttributeMaxDynamicSharedMemorySize, GEMM_SMEM);

    // Conversions (launches 0-2)
    {
        size_t tot4 = (size_t)NNODES * (K1PAD / 4);
        quantize_pad_kernel<<<(unsigned)((tot4 + 255) / 256), 256>>>(
            features, fa, NNODES, D_IN, K1PAD);
        dim3 tb(32, 8);
        dim3 tg1(K1PAD / 32, N1PAD / 32);
        transpose_f16_tiled_kernel<<<tg1, tb>>>(W1, w1t, D_IN, D_H1, K1PAD, N1PAD);
        dim3 tg2(K2PAD / 32, N2PAD / 32);
        transpose_f16_tiled_kernel<<<tg2, tb>>>(W2, w2t, D_H1, D_H2, K2PAD, N2PAD);
    }

    // GEMM 1 (launch 3 — ncu capture slot): t1 = fa @ W1^T (fp16 out)
    {
        dim3 grid(N1PAD / B_ROWS, (NNODES + A_ROWS - 1) / A_ROWS);
        hmma_gemm_f16_kernel<<<grid, 256, GEMM_SMEM>>>(fa, w1t, t1,
                                                       NNODES, D_H1, K1PAD);
    }

    // CSR build
    zero_counts_kernel<<<(NNODES + 255) / 256, 256>>>();
    count_kernel<<<(NEDGES + 255) / 256, 256>>>(dst);
    scan_kernel<<<1, 1024>>>();
    fill_kernel<<<(NEDGES + 255) / 256, 256>>>(src, dst);

    // Layer 1 aggregation: x1 = relu(agg(t1)+b1) (fp16, padded)
    agg1_kernel<<<NNODES, 128>>>(t1, b1, x1);

    // Layer 2: t2 = x1 @ W2^T (fp16 out); x2 = relu(agg(t2)+b2) (fp32)
    {
        dim3 grid(N2PAD / B_ROWS, (NNODES + A_ROWS - 1) / A_ROWS);
        hmma_gemm_f16_kernel<<<grid, 256, GEMM_SMEM>>>(x1, w2t, t2,
                                                       NNODES, D_H2, K2PAD);
        agg2_kernel<<<NNODES, 128>>>(t2, b2, x2);
    }

    // Output layer
    {
        int blocks = (NNODES + 7) / 8;
        out_layer_kernel<<<blocks, 256>>>(x2, W3, b3, out);
    }
}

// round 9
// speedup vs baseline: 1.1624x; 1.1624x over previous
#include <cuda_runtime.h>
#include <cuda_fp16.h>
#include <cstdint>

// Problem constants
#define NNODES 20000
#define NEDGES 200000
#define D_IN   1433
#define D_H1   1000
#define D_H2   500
#define D_OUT  7

// Padded GEMM dims
#define K1PAD  1472   // >= 1433, mult of 64
#define K2PAD  1024   // >= 1000, mult of 64
#define N1PAD  1024   // >= 1000, mult of 128
#define N2PAD  512    // >= 500,  mult of 128

// ---------------------------------------------------------------------------
// Device scratch
// ---------------------------------------------------------------------------
__device__ __align__(256) __half g_fa[(size_t)NNODES * K1PAD];
__device__ __align__(256) __half g_w1t[(size_t)N1PAD * K1PAD];
__device__ __align__(256) __half g_x1[(size_t)NNODES * K2PAD];
__device__ __align__(256) __half g_w2t[(size_t)N2PAD * K2PAD];
__device__ __align__(256) __half g_t1[(size_t)NNODES * D_H1];
__device__ __align__(256) __half g_t2[(size_t)NNODES * D_H2];
__device__ __align__(256) float  g_x2[(size_t)NNODES * D_H2];
__device__ int g_count[NNODES];
__device__ int g_pos[NNODES];
__device__ int g_offs[NNODES + 1];
__device__ int g_eidx[NEDGES];

// ---------------------------------------------------------------------------
// PTX helpers
// ---------------------------------------------------------------------------
__device__ __forceinline__ uint32_t smem_to_u32(const void* p) {
    uint32_t a;
    asm("{ .reg .u64 t; cvta.to.shared.u64 t, %1; cvt.u32.u64 %0, t; }"
        : "=r"(a) : "l"(p));
    return a;
}

__device__ __forceinline__ void cp_async16(uint32_t sdst, const void* gsrc, bool ok) {
    int sz = ok ? 16 : 0;
    asm volatile("cp.async.cg.shared.global [%0], [%1], 16, %2;\n"
                 :: "r"(sdst), "l"(gsrc), "r"(sz));
}
#define CP_COMMIT() asm volatile("cp.async.commit_group;\n" ::: "memory")
#define CP_WAIT(n)  asm volatile("cp.async.wait_group %0;\n" :: "n"(n) : "memory")

__device__ __forceinline__ void ldm_x4(uint32_t& r0, uint32_t& r1, uint32_t& r2,
                                       uint32_t& r3, uint32_t addr) {
    asm volatile("ldmatrix.sync.aligned.m8n8.x4.shared.b16 {%0,%1,%2,%3}, [%4];"
                 : "=r"(r0), "=r"(r1), "=r"(r2), "=r"(r3) : "r"(addr));
}

__device__ __forceinline__ void mma_f16(float* c, const uint32_t* a, const uint32_t* b) {
    asm volatile(
        "mma.sync.aligned.m16n8k16.row.col.f32.f16.f16.f32 "
        "{%0,%1,%2,%3}, {%4,%5,%6,%7}, {%8,%9}, {%0,%1,%2,%3};"
        : "+f"(c[0]), "+f"(c[1]), "+f"(c[2]), "+f"(c[3])
        : "r"(a[0]), "r"(a[1]), "r"(a[2]), "r"(a[3]), "r"(b[0]), "r"(b[1]));
}

__device__ __forceinline__ uint32_t pack_f16x2(float a, float b) {
    __half2 h = __floats2half2_rn(a, b);
    return *reinterpret_cast<uint32_t*>(&h);
}

struct __align__(8) half4 { __half2 a, b; };

// ---------------------------------------------------------------------------
// CSR build (g_count/g_pos zeroed inside quantize_pad_kernel)
// ---------------------------------------------------------------------------
__global__ void count_kernel(const int* __restrict__ dst) {
    int e = blockIdx.x * blockDim.x + threadIdx.x;
    if (e < NEDGES) atomicAdd(&g_count[dst[e]], 1);
}
__global__ void scan_kernel() {
    __shared__ int part[1024];
    const int tid = threadIdx.x;
    const int CH = (NNODES + 1023) / 1024;
    const int base = tid * CH;
    int s = 0;
    for (int i = 0; i < CH; ++i) {
        int idx = base + i;
        if (idx < NNODES) s += g_count[idx];
    }
    part[tid] = s;
    __syncthreads();
    for (int off = 1; off < 1024; off <<= 1) {
        int v = (tid >= off) ? part[tid - off] : 0;
        __syncthreads();
        part[tid] += v;
        __syncthreads();
    }
    int run = part[tid] - s;
    for (int i = 0; i < CH; ++i) {
        int idx = base + i;
        if (idx < NNODES) { g_offs[idx] = run; run += g_count[idx]; }
    }
    if (tid == 1023) g_offs[NNODES] = part[1023];
}
__global__ void fill_kernel(const int* __restrict__ src, const int* __restrict__ dst) {
    int e = blockIdx.x * blockDim.x + threadIdx.x;
    if (e < NEDGES) {
        int d = dst[e];
        int p = atomicAdd(&g_pos[d], 1);
        g_eidx[g_offs[d] + p] = src[e];
    }
}

// ---------------------------------------------------------------------------
// Conversion: fp32 -> fp16, zero-padded; 4 elems/thread. Also zeroes CSR counters.
// ---------------------------------------------------------------------------
__global__ void quantize_pad_kernel(const float* __restrict__ src,
                                    __half* __restrict__ dstq,
                                    int M, int K, int Kpad) {
    size_t idx4 = (size_t)blockIdx.x * blockDim.x + threadIdx.x;
    // fold: zero CSR counters (runs before count_kernel in stream order)
    if (idx4 < NNODES) { g_count[(int)idx4] = 0; g_pos[(int)idx4] = 0; }
    size_t total4 = (size_t)M * (Kpad >> 2);
    if (idx4 >= total4) return;
    int gpr = Kpad >> 2;
    int r = (int)(idx4 / gpr);
    int c = (int)(idx4 % gpr) << 2;
    float v[4];
#pragma unroll
    for (int j = 0; j < 4; ++j) {
        int cj = c + j;
        v[j] = (cj < K) ? src[(size_t)r * K + cj] : 0.f;
    }
    size_t o = (size_t)r * Kpad + c;
    *reinterpret_cast<uint2*>(dstq + o) =
        make_uint2(pack_f16x2(v[0], v[1]), pack_f16x2(v[2], v[3]));
}

// Tiled transpose: W [K,N] fp32 row-major -> Wt fp16 [Npad][Kpad], zero-padded
__global__ void transpose_f16_tiled_kernel(const float* __restrict__ W,
                                           __half* __restrict__ t,
                                           int K, int N, int Kpad, int Npad) {
    __shared__ float tile[32][33];
    const int k0 = blockIdx.x * 32;
    const int n0 = blockIdx.y * 32;
    const int tx = threadIdx.x;
    const int ty = threadIdx.y;
#pragma unroll
    for (int j = 0; j < 32; j += 8) {
        int k = k0 + ty + j, n = n0 + tx;
        tile[ty + j][tx] = (k < K && n < N) ? W[(size_t)k * N + n] : 0.f;
    }
    __syncthreads();
#pragma unroll
    for (int j = 0; j < 32; j += 8) {
        int n = n0 + ty + j, k = k0 + tx;
        if (n < Npad && k < Kpad)
            t[(size_t)n * Kpad + k] = __float2half(tile[tx][ty + j]);
    }
}

// ---------------------------------------------------------------------------
// HMMA GEMM: persistent CTAs, CTA tile 128x128, 8 warps (4m x 2n),
// warp tile 32x64, 3-stage cp.async pipeline, BK=64, occ 2,
// B-fragment double buffering within the ks loop.
// ---------------------------------------------------------------------------
#define BK 64
#define ROW_H 72                                // halves per smem row (64 + 8)
#define MAT_BYTES ((uint32_t)(128 * ROW_H * 2)) // 18432
#define B_OFF     MAT_BYTES
#define STAGE_BYTES (2 * MAT_BYTES)             // 36864
#define NSTAGE 3
#define GEMM_SMEM (NSTAGE * STAGE_BYTES)        // 110592
#define GEMM_GRID 296                           // 148 SMs x occ 2

__global__ __launch_bounds__(256, 2)
void hmma_gemm_f16_kernel(const __half* __restrict__ a,
                          const __half* __restrict__ b,
                          __half* __restrict__ C,
                          int M, int Nreal, int Kpad,
                          int mtiles, int ntiles) {
    extern __shared__ __half smem[];
    const uint32_t smem_u32 = smem_to_u32(smem);
    const int t = threadIdx.x;
    const int lane = t & 31;
    const int wid = t >> 5;
    const int wm = wid & 3;
    const int wn = wid >> 2;
    const int nchunk = Kpad / BK;
    const int ntotal = mtiles * ntiles;

    for (int tile = blockIdx.x; tile < ntotal; tile += gridDim.x) {
        const int m0 = (tile / ntiles) * 128;
        const int n0 = (tile % ntiles) * 128;

        float acc[2][8][4];
#pragma unroll
        for (int i = 0; i < 2; ++i)
#pragma unroll
            for (int j = 0; j < 8; ++j)
#pragma unroll
                for (int k = 0; k < 4; ++k) acc[i][j][k] = 0.f;

        auto load_stage = [&](int c) {
            const int slot = c % NSTAGE;
            const int k0 = c * BK;
            const uint32_t sbase = smem_u32 + slot * STAGE_BYTES;
#pragma unroll
            for (int i = 0; i < 4; ++i) {
                int idx = t + i * 256;
                int row = idx >> 3;
                int ch = idx & 7;
                uint32_t off = (uint32_t)(row * ROW_H + ch * 8) * 2;
                int gm = m0 + row;
                bool ok = gm < M;
                int gmc = ok ? gm : 0;
                size_t goa = (size_t)gmc * Kpad + k0 + ch * 8;
                cp_async16(sbase + off, a + goa, ok);
                size_t gob = (size_t)(n0 + row) * Kpad + k0 + ch * 8;
                cp_async16(sbase + off + B_OFF, b + gob, true);
            }
            CP_COMMIT();
        };

        load_stage(0);
        load_stage(1);

        for (int c = 0; c < nchunk; ++c) {
            if (c + 1 < nchunk) { CP_WAIT(1); } else { CP_WAIT(0); }
            __syncthreads();
            if (c + 2 < nchunk) load_stage(c + 2);

            const uint32_t sb = smem_u32 + (uint32_t)(c % NSTAGE) * STAGE_BYTES;
            const int brr = (lane & 7) + (lane >> 4) * 8;
            const int bko = ((lane >> 3) & 1) * 8;
            const int ar = lane & 15;
            const int ako = (lane >> 4) * 8;

            // B-fragment double buffer: prefetch ks=0
            uint32_t bf[2][8][2];
            {
#pragma unroll
                for (int ng = 0; ng < 4; ++ng) {
                    uint32_t addr = sb + B_OFF +
                        (uint32_t)((wn * 64 + ng * 16 + brr) * ROW_H + bko) * 2;
                    uint32_t r0, r1, r2, r3;
                    ldm_x4(r0, r1, r2, r3, addr);
                    bf[0][2 * ng][0] = r0; bf[0][2 * ng][1] = r1;
                    bf[0][2 * ng + 1][0] = r2; bf[0][2 * ng + 1][1] = r3;
                }
            }
#pragma unroll
            for (int ks = 0; ks < 4; ++ks) {
                const int cur = ks & 1;
                const int nxt = cur ^ 1;
                // A fragments for this ks
                uint32_t af[2][4];
                {
                    int ak = ks * 16 + ako;
#pragma unroll
                    for (int mt = 0; mt < 2; ++mt) {
                        uint32_t addr = sb +
                            (uint32_t)((wm * 32 + mt * 16 + ar) * ROW_H + ak) * 2;
                        ldm_x4(af[mt][0], af[mt][1], af[mt][2], af[mt][3], addr);
                    }
                }
                // prefetch B fragments for ks+1
                if (ks < 3) {
                    int bk = (ks + 1) * 16 + bko;
#pragma unroll
                    for (int ng = 0; ng < 4; ++ng) {
                        uint32_t addr = sb + B_OFF +
                            (uint32_t)((wn * 64 + ng * 16 + brr) * ROW_H + bk) * 2;
                        uint32_t r0, r1, r2, r3;
                        ldm_x4(r0, r1, r2, r3, addr);
                        bf[nxt][2 * ng][0] = r0; bf[nxt][2 * ng][1] = r1;
                        bf[nxt][2 * ng + 1][0] = r2; bf[nxt][2 * ng + 1][1] = r3;
                    }
                }
#pragma unroll
                for (int mt = 0; mt < 2; ++mt) {
#pragma unroll
                    for (int nt = 0; nt < 8; ++nt) {
                        mma_f16(acc[mt][nt], af[mt], bf[cur][nt]);
                    }
                }
            }
        }

        // epilogue: fp16 packed stores
#pragma unroll
        for (int mt = 0; mt < 2; ++mt) {
            int gr0 = m0 + wm * 32 + mt * 16 + (lane >> 2);
#pragma unroll
            for (int nt = 0; nt < 8; ++nt) {
                int gc = n0 + wn * 64 + nt * 8 + (lane & 3) * 2;
                if (gc >= Nreal) continue;
                if (gr0 < M) {
                    *reinterpret_cast<uint32_t*>(&C[(size_t)gr0 * Nreal + gc]) =
                        pack_f16x2(acc[mt][nt][0], acc[mt][nt][1]);
                }
                if (gr0 + 8 < M) {
                    *reinterpret_cast<uint32_t*>(&C[(size_t)(gr0 + 8) * Nreal + gc]) =
                        pack_f16x2(acc[mt][nt][2], acc[mt][nt][3]);
                }
            }
        }
        __syncthreads();   // smem reuse safety before next tile's load_stage
    }
}

// ---------------------------------------------------------------------------
// Aggregation 1: x1[i,:] = relu(b1 + sum_j t1[j,:]) -> fp16, padded to K2PAD
// ---------------------------------------------------------------------------
__global__ __launch_bounds__(128)
void agg1_kernel(const __half* __restrict__ t,
                 const float* __restrict__ bias,
                 __half* __restrict__ x1) {
    __shared__ int nbr[512];
    const int node = blockIdx.x;
    const int beg = g_offs[node], end = g_offs[node + 1];
    const int deg = end - beg;
    const int* elist;
    if (deg <= 512) {
        for (int i = threadIdx.x; i < deg; i += blockDim.x) nbr[i] = g_eidx[beg + i];
        __syncthreads();
        elist = nbr;
    } else {
        elist = g_eidx + beg;
    }
    const int c = threadIdx.x << 3;
    if (c < D_H1) {
        float a[8];
#pragma unroll
        for (int j = 0; j < 8; ++j) a[j] = bias[c + j];
        for (int e = 0; e < deg; ++e) {
            const uint4 v = *reinterpret_cast<const uint4*>(
                t + (size_t)elist[e] * D_H1 + c);
            const __half2* h = reinterpret_cast<const __half2*>(&v);
#pragma unroll
            for (int j = 0; j < 4; ++j) {
                float2 p = __half22float2(h[j]);
                a[2 * j] += p.x;
                a[2 * j + 1] += p.y;
            }
        }
        uint4 o;
        uint32_t* ow = reinterpret_cast<uint32_t*>(&o);
#pragma unroll
        for (int j = 0; j < 4; ++j)
            ow[j] = pack_f16x2(fmaxf(a[2 * j], 0.f), fmaxf(a[2 * j + 1], 0.f));
        *reinterpret_cast<uint4*>(x1 + (size_t)node * K2PAD + c) = o;
    } else {
        *reinterpret_cast<uint4*>(x1 + (size_t)node * K2PAD + c) =
            make_uint4(0u, 0u, 0u, 0u);
    }
}

// Aggregation 2: x2[i,:] = relu(b2 + sum_j t2[j,:]) -> fp32.
__global__ __launch_bounds__(128)
void agg2_kernel(const __half* __restrict__ t,
                 const float* __restrict__ bias,
                 float* __restrict__ out) {
    __shared__ int nbr[512];
    const int node = blockIdx.x;
    const int beg = g_offs[node], end = g_offs[node + 1];
    const int deg = end - beg;
    const int* elist;
    if (deg <= 512) {
        for (int i = threadIdx.x; i < deg; i += blockDim.x) nbr[i] = g_eidx[beg + i];
        __syncthreads();
        elist = nbr;
    } else {
        elist = g_eidx + beg;
    }
    const int c = threadIdx.x << 2;
    if (c >= D_H2) return;
    float a0 = bias[c], a1 = bias[c + 1], a2 = bias[c + 2], a3 = bias[c + 3];
    for (int e = 0; e < deg; ++e) {
        const half4 v = *reinterpret_cast<const half4*>(
            t + (size_t)elist[e] * D_H2 + c);
        float2 p = __half22float2(v.a);
        float2 q = __half22float2(v.b);
        a0 += p.x; a1 += p.y; a2 += q.x; a3 += q.y;
    }
    float4 r = make_float4(fmaxf(a0, 0.f), fmaxf(a1, 0.f),
                           fmaxf(a2, 0.f), fmaxf(a3, 0.f));
    *reinterpret_cast<float4*>(out + (size_t)node * D_H2 + c) = r;
}

// ---------------------------------------------------------------------------
// Output layer: out[i,:7] = relu(x2[i,:] @ W3 + b3), one warp per row
// ---------------------------------------------------------------------------
__global__ void out_layer_kernel(const float* __restrict__ x2,
                                 const float* __restrict__ W3,
                                 const float* __restrict__ b3,
                                 float* __restrict__ out) {
    __shared__ float Ws[D_H2 * D_OUT];
    for (int i = threadIdx.x; i < D_H2 * D_OUT; i += blockDim.x) Ws[i] = W3[i];
    __syncthreads();
    const int warp = (blockIdx.x * blockDim.x + threadIdx.x) >> 5;
    const int lane = threadIdx.x & 31;
    if (warp >= NNODES) return;
    float acc[D_OUT] = {0.f, 0.f, 0.f, 0.f, 0.f, 0.f, 0.f};
    const float* row = x2 + (size_t)warp * D_H2;
    for (int k = lane; k < D_H2; k += 32) {
        float v = row[k];
#pragma unroll
        for (int j = 0; j < D_OUT; ++j) acc[j] += v * Ws[k * D_OUT + j];
    }
#pragma unroll
    for (int j = 0; j < D_OUT; ++j) {
#pragma unroll
        for (int off = 16; off > 0; off >>= 1)
            acc[j] += __shfl_xor_sync(0xFFFFFFFFu, acc[j], off);
    }
    if (lane == 0) {
#pragma unroll
        for (int j = 0; j < D_OUT; ++j)
            out[(size_t)warp * D_OUT + j] = fmaxf(acc[j] + b3[j], 0.f);
    }
}

// ---------------------------------------------------------------------------
// Launch — gemm1 stays at host-issue index 3 (the ncu capture slot).
// ---------------------------------------------------------------------------
extern "C" void kernel_launch(void* const* d_in, const int* in_sizes, int n_in,
                              void* d_out, int out_size) {
    const float* features = (const float*)d_in[0];
    const int*   src      = (const int*)  d_in[1];
    const int*   dst      = (const int*)  d_in[2];
    const float* W1       = (const float*)d_in[3];
    const float* b1       = (const float*)d_in[4];
    const float* W2       = (const float*)d_in[5];
    const float* b2       = (const float*)d_in[6];
    const float* W3       = (const float*)d_in[7];
    const float* b3       = (const float*)d_in[8];
    float* out = (float*)d_out;

    __half *fa, *w1t, *x1, *w2t, *t1, *t2;
    float *x2;
    cudaGetSymbolAddress((void**)&fa, g_fa);
    cudaGetSymbolAddress((void**)&w1t, g_w1t);
    cudaGetSymbolAddress((void**)&x1, g_x1);
    cudaGetSymbolAddress((void**)&w2t, g_w2t);
    cudaGetSymbolAddress((void**)&t1, g_t1);
    cudaGetSymbolAddress((void**)&t2, g_t2);
    cudaGetSymbolAddress((void**)&x2, g_x2);

    cudaFuncSetAttribute(hmma_gemm_f16_kernel,
                         cudaFuncAttributeMaxDynamicSharedMemorySize, GEMM_SMEM);

    // Launch 0: quantize features (+ zero CSR counters)
    {
        size_t tot4 = (size_t)NNODES * (K1PAD / 4);
        quantize_pad_kernel<<<(unsigned)((tot4 + 255) / 256), 256>>>(
            features, fa, NNODES, D_IN, K1PAD);
    }
    // Launches 1-2: weight transposes
    {
        dim3 tb(32, 8);
        dim3 tg1(K1PAD / 32, N1PAD / 32);
        transpose_f16_tiled_kernel<<<tg1, tb>>>(W1, w1t, D_IN, D_H1, K1PAD, N1PAD);
        dim3 tg2(K2PAD / 32, N2PAD / 32);
        transpose_f16_tiled_kernel<<<tg2, tb>>>(W2, w2t, D_H1, D_H2, K2PAD, N2PAD);
    }

    // Launch 3 (ncu capture slot): GEMM 1, persistent grid
    {
        int mtiles = (NNODES + 127) / 128;         // 157
        int ntiles = N1PAD / 128;                  // 8
        hmma_gemm_f16_kernel<<<GEMM_GRID, 256, GEMM_SMEM>>>(
            fa, w1t, t1, NNODES, D_H1, K1PAD, mtiles, ntiles);
    }

    // CSR build
    count_kernel<<<(NEDGES + 255) / 256, 256>>>(dst);
    scan_kernel<<<1, 1024>>>();
    fill_kernel<<<(NEDGES + 255) / 256, 256>>>(src, dst);

    // Layer 1 aggregation
    agg1_kernel<<<NNODES, 128>>>(t1, b1, x1);

    // Layer 2: GEMM 2 (persistent) + aggregation
    {
        int mtiles = (NNODES + 127) / 128;         // 157
        int ntiles = N2PAD / 128;                  // 4
        hmma_gemm_f16_kernel<<<GEMM_GRID, 256, GEMM_SMEM>>>(
            x1, w2t, t2, NNODES, D_H2, K2PAD, mtiles, ntiles);
        agg2_kernel<<<NNODES, 128>>>(t2, b2, x2);
    }

    // Output layer
    {
        int blocks = (NNODES + 7) / 8;
        out_layer_kernel<<<blocks, 256>>>(x2, W3, b3, out);
    }
}